// round 1
// baseline (speedup 1.0000x reference)
#include <cuda_runtime.h>
#include <math.h>

// ---------------------------------------------------------------------------
// SelfAttentionV3: B=4, S=2048, E=1024
// out = (softmax(mask( (X Wqkv^T + b)_q (X Wqkv^T + b)_k^T / 32 )) V) Wout^T + bout
// All fp32 SIMT baseline (rel_err ~1e-6). 5 launches, static device scratch.
// ---------------------------------------------------------------------------

#define EMBED 1024
#define BATCH 4
#define SEQ   2048
#define ROWS  (BATCH * SEQ)        // 8192

// scratch (static __device__ arrays -- allocation-guard safe)
__device__ float g_qkv[(size_t)ROWS * 3 * EMBED];   // 96 MB  [8192, 3072]
__device__ float g_att[(size_t)BATCH * SEQ * SEQ];  // 64 MB  [4, 2048, 2048]
__device__ float g_ctx[(size_t)ROWS * EMBED];       // 32 MB  [8192, 1024]

// ---------------------------------------------------------------------------
// Tiled SGEMM: C = scale * (A x B(^T)) + bias
//   A: [M, K] row-major, lda
//   BT=true : B: [N, K] row-major, ldb   (C = A B^T)
//   BT=false: B: [K, N] row-major, ldb   (C = A B)
//   C: [M, N] row-major, ldc
// blockIdx.z batches via aBS/bBS/cBS element strides.
// Requires M%128==0, N%128==0, K%8==0, K-cols 4-float aligned.
// ---------------------------------------------------------------------------
#define BM 128
#define BN 128
#define BK 8

template <bool BT, bool HAS_BIAS>
__global__ __launch_bounds__(256) void sgemm_kernel(
    const float* __restrict__ A, const float* __restrict__ B,
    const float* __restrict__ bias, float* __restrict__ C,
    int M, int N, int K, int lda, int ldb, int ldc,
    long aBS, long bBS, long cBS, float scale)
{
    __shared__ float As[BK][BM];
    __shared__ float Bs[BK][BN];

    const int bm = blockIdx.y * BM;
    const int bn = blockIdx.x * BN;
    A += (long)blockIdx.z * aBS;
    B += (long)blockIdx.z * bBS;
    C += (long)blockIdx.z * cBS;

    const int tid = threadIdx.x;
    const int tx = tid & 15;    // 0..15 -> column groups
    const int ty = tid >> 4;    // 0..15 -> row groups

    // A-tile load mapping (K-contiguous): 128 rows x 8 k = 256 float4
    const int arow = tid >> 1;          // 0..127
    const int acol = (tid & 1) * 4;     // 0 or 4
    // B-tile load mapping for NN (N-contiguous): 8 k-rows x 128 n
    const int nkr = tid >> 5;           // 0..7
    const int nkc = (tid & 31) * 4;     // 0..124

    float acc[8][8];
#pragma unroll
    for (int i = 0; i < 8; i++)
#pragma unroll
        for (int j = 0; j < 8; j++) acc[i][j] = 0.f;

    for (int k0 = 0; k0 < K; k0 += BK) {
        // load A tile (transpose into As[k][m])
        float4 av = *reinterpret_cast<const float4*>(
            &A[(long)(bm + arow) * lda + k0 + acol]);
        As[acol + 0][arow] = av.x;
        As[acol + 1][arow] = av.y;
        As[acol + 2][arow] = av.z;
        As[acol + 3][arow] = av.w;

        if (BT) {
            // B[n, k] K-contiguous -> transpose into Bs[k][n]
            float4 bv = *reinterpret_cast<const float4*>(
                &B[(long)(bn + arow) * ldb + k0 + acol]);
            Bs[acol + 0][arow] = bv.x;
            Bs[acol + 1][arow] = bv.y;
            Bs[acol + 2][arow] = bv.z;
            Bs[acol + 3][arow] = bv.w;
        } else {
            // B[k, n] N-contiguous -> direct
            float4 bv = *reinterpret_cast<const float4*>(
                &B[(long)(k0 + nkr) * ldb + bn + nkc]);
            *reinterpret_cast<float4*>(&Bs[nkr][nkc]) = bv;
        }
        __syncthreads();

#pragma unroll
        for (int kk = 0; kk < BK; kk++) {
            float4 a0 = *reinterpret_cast<const float4*>(&As[kk][ty * 4]);
            float4 a1 = *reinterpret_cast<const float4*>(&As[kk][64 + ty * 4]);
            float4 b0 = *reinterpret_cast<const float4*>(&Bs[kk][tx * 4]);
            float4 b1 = *reinterpret_cast<const float4*>(&Bs[kk][64 + tx * 4]);
            float a[8] = {a0.x, a0.y, a0.z, a0.w, a1.x, a1.y, a1.z, a1.w};
            float b[8] = {b0.x, b0.y, b0.z, b0.w, b1.x, b1.y, b1.z, b1.w};
#pragma unroll
            for (int i = 0; i < 8; i++)
#pragma unroll
                for (int j = 0; j < 8; j++)
                    acc[i][j] = fmaf(a[i], b[j], acc[i][j]);
        }
        __syncthreads();
    }

    // epilogue: rows {ty*4+i, 64+ty*4+i}, cols {tx*4+j, 64+tx*4+j}
#pragma unroll
    for (int i = 0; i < 8; i++) {
        int r = bm + ((i < 4) ? (ty * 4 + i) : (64 + ty * 4 + (i - 4)));
#pragma unroll
        for (int g = 0; g < 2; g++) {
            int c = bn + g * 64 + tx * 4;
            float4 v;
            v.x = acc[i][g * 4 + 0] * scale;
            v.y = acc[i][g * 4 + 1] * scale;
            v.z = acc[i][g * 4 + 2] * scale;
            v.w = acc[i][g * 4 + 3] * scale;
            if (HAS_BIAS) {
                v.x += bias[c + 0];
                v.y += bias[c + 1];
                v.z += bias[c + 2];
                v.w += bias[c + 3];
            }
            *reinterpret_cast<float4*>(&C[(long)r * ldc + c]) = v;
        }
    }
}

// ---------------------------------------------------------------------------
// Row softmax with mask. One block per (b, q) row. S = 2048, 256 threads,
// 8 elements per thread.
// ---------------------------------------------------------------------------
__global__ __launch_bounds__(256) void softmax_kernel(
    float* __restrict__ att, const int* __restrict__ mask, int S)
{
    const long row = blockIdx.x;
    float* a = att + row * S;
    const int* m = mask + row * S;
    const int tid = threadIdx.x;

    __shared__ float red_max[8];
    __shared__ float red_sum[8];

    float v[8];
    float mx = -INFINITY;
#pragma unroll
    for (int i = 0; i < 8; i++) {
        int idx = tid + i * 256;
        float x = a[idx];
        x = (m[idx] != 0) ? x : -INFINITY;
        v[i] = x;
        mx = fmaxf(mx, x);
    }
    // block max
#pragma unroll
    for (int o = 16; o > 0; o >>= 1)
        mx = fmaxf(mx, __shfl_xor_sync(0xffffffffu, mx, o));
    if ((tid & 31) == 0) red_max[tid >> 5] = mx;
    __syncthreads();
    float bmax = red_max[0];
#pragma unroll
    for (int w = 1; w < 8; w++) bmax = fmaxf(bmax, red_max[w]);

    float s = 0.f;
#pragma unroll
    for (int i = 0; i < 8; i++) {
        v[i] = __expf(v[i] - bmax);
        s += v[i];
    }
#pragma unroll
    for (int o = 16; o > 0; o >>= 1)
        s += __shfl_xor_sync(0xffffffffu, s, o);
    if ((tid & 31) == 0) red_sum[tid >> 5] = s;
    __syncthreads();
    float total = 0.f;
#pragma unroll
    for (int w = 0; w < 8; w++) total += red_sum[w];

    float inv = 1.f / total;
#pragma unroll
    for (int i = 0; i < 8; i++) {
        int idx = tid + i * 256;
        a[idx] = v[i] * inv;
    }
}

// ---------------------------------------------------------------------------
extern "C" void kernel_launch(void* const* d_in, const int* in_sizes, int n_in,
                              void* d_out, int out_size)
{
    const float* X    = (const float*)d_in[0];
    const int*   mask = (const int*)  d_in[1];
    const float* Wqkv = (const float*)d_in[2];
    const float* bqkv = (const float*)d_in[3];
    const float* Wout = (const float*)d_in[4];
    const float* bout = (const float*)d_in[5];
    float* out = (float*)d_out;

    float *qkv, *att, *ctx;
    cudaGetSymbolAddress((void**)&qkv, g_qkv);
    cudaGetSymbolAddress((void**)&att, g_att);
    cudaGetSymbolAddress((void**)&ctx, g_ctx);

    const float inv_sqrt_e = 1.0f / 32.0f;   // 1/sqrt(1024)

    // 1) qkv = X Wqkv^T + bqkv        [8192, 3072]
    {
        dim3 grid(3 * EMBED / BN, ROWS / BM, 1);
        sgemm_kernel<true, true><<<grid, 256>>>(
            X, Wqkv, bqkv, qkv,
            ROWS, 3 * EMBED, EMBED, EMBED, EMBED, 3 * EMBED,
            0, 0, 0, 1.0f);
    }
    // 2) att[b] = Q[b] K[b]^T / 32     [4, 2048, 2048]
    {
        dim3 grid(SEQ / BN, SEQ / BM, BATCH);
        sgemm_kernel<true, false><<<grid, 256>>>(
            qkv, qkv + EMBED, nullptr, att,
            SEQ, SEQ, EMBED, 3 * EMBED, 3 * EMBED, SEQ,
            (long)SEQ * 3 * EMBED, (long)SEQ * 3 * EMBED, (long)SEQ * SEQ,
            inv_sqrt_e);
    }
    // 3) softmax rows with mask
    softmax_kernel<<<BATCH * SEQ, 256>>>(att, mask, SEQ);

    // 4) ctx[b] = att[b] V[b]          [4, 2048, 1024]
    {
        dim3 grid(EMBED / BN, SEQ / BM, BATCH);
        sgemm_kernel<false, false><<<grid, 256>>>(
            att, qkv + 2 * EMBED, nullptr, ctx,
            SEQ, EMBED, SEQ, SEQ, 3 * EMBED, EMBED,
            (long)SEQ * SEQ, (long)SEQ * 3 * EMBED, (long)SEQ * EMBED,
            1.0f);
    }
    // 5) out = ctx Wout^T + bout       [8192, 1024]
    {
        dim3 grid(EMBED / BN, ROWS / BM, 1);
        sgemm_kernel<true, true><<<grid, 256>>>(
            ctx, Wout, bout, out,
            ROWS, EMBED, EMBED, EMBED, EMBED, EMBED,
            0, 0, 0, 1.0f);
    }
}

// round 3
// speedup vs baseline: 2.5981x; 2.5981x over previous
#include <cuda_runtime.h>
#include <cuda_bf16.h>
#include <cstdint>
#include <math.h>

// ---------------------------------------------------------------------------
// SelfAttentionV3 (B=4, S=2048, E=1024) via bf16x3 split-precision HMMA GEMMs.
// Non-'a' PTX only: mma.sync + ldmatrix + cp.async (tcgen05 is arch-gated off).
// ---------------------------------------------------------------------------

#define EMBED 1024
#define BATCH 4
#define SEQ   2048
#define ROWS  (BATCH * SEQ)   // 8192

typedef __nv_bfloat16 bf16;

// ---------------- static scratch (no allocs allowed) -----------------------
__device__ bf16 g_Xhi[(size_t)ROWS * EMBED];
__device__ bf16 g_Xlo[(size_t)ROWS * EMBED];
__device__ bf16 g_Wqkvhi[(size_t)3 * EMBED * EMBED];
__device__ bf16 g_Wqkvlo[(size_t)3 * EMBED * EMBED];
__device__ bf16 g_Wouthi[(size_t)EMBED * EMBED];
__device__ bf16 g_Woutlo[(size_t)EMBED * EMBED];
__device__ bf16 g_qkvhi[(size_t)ROWS * 3 * EMBED];
__device__ bf16 g_qkvlo[(size_t)ROWS * 3 * EMBED];
__device__ float g_att[(size_t)BATCH * SEQ * SEQ];
__device__ bf16 g_atthi[(size_t)BATCH * SEQ * SEQ];
__device__ bf16 g_attlo[(size_t)BATCH * SEQ * SEQ];
__device__ bf16 g_vthi[(size_t)BATCH * EMBED * SEQ];
__device__ bf16 g_vtlo[(size_t)BATCH * EMBED * SEQ];
__device__ bf16 g_ctxhi[(size_t)ROWS * EMBED];
__device__ bf16 g_ctxlo[(size_t)ROWS * EMBED];

// ---------------- PTX helpers ----------------------------------------------
__device__ __forceinline__ uint32_t smem_u32(const void* p) {
    uint32_t a;
    asm("{ .reg .u64 t; cvta.to.shared.u64 t, %1; cvt.u32.u64 %0, t; }"
        : "=r"(a) : "l"(p));
    return a;
}
__device__ __forceinline__ void cp16(uint32_t dst, const void* src) {
    asm volatile("cp.async.cg.shared.global [%0], [%1], 16;"
                 :: "r"(dst), "l"(src) : "memory");
}
__device__ __forceinline__ void cp_commit() {
    asm volatile("cp.async.commit_group;" ::: "memory");
}
template <int N>
__device__ __forceinline__ void cp_wait() {
    asm volatile("cp.async.wait_group %0;" :: "n"(N) : "memory");
}
__device__ __forceinline__ void ldm4(uint32_t* r, uint32_t addr) {
    asm volatile("ldmatrix.sync.aligned.m8n8.x4.shared.b16 {%0,%1,%2,%3}, [%4];"
                 : "=r"(r[0]), "=r"(r[1]), "=r"(r[2]), "=r"(r[3]) : "r"(addr));
}
__device__ __forceinline__ void mma16816(float* c, const uint32_t* a, const uint32_t* b) {
    asm volatile("mma.sync.aligned.m16n8k16.row.col.f32.bf16.bf16.f32 "
                 "{%0,%1,%2,%3}, {%4,%5,%6,%7}, {%8,%9}, {%0,%1,%2,%3};"
                 : "+f"(c[0]), "+f"(c[1]), "+f"(c[2]), "+f"(c[3])
                 : "r"(a[0]), "r"(a[1]), "r"(a[2]), "r"(a[3]), "r"(b[0]), "r"(b[1]));
}
__device__ __forceinline__ void split1(float x, bf16& h, bf16& l) {
    h = __float2bfloat16(x);
    l = __float2bfloat16(x - __bfloat162float(h));
}
__device__ __forceinline__ uint32_t pack2(bf16 a, bf16 b) {
    uint16_t ua = *reinterpret_cast<uint16_t*>(&a);
    uint16_t ub = *reinterpret_cast<uint16_t*>(&b);
    return (uint32_t)ua | ((uint32_t)ub << 16);
}

// ---------------------------------------------------------------------------
// bf16x3 GEMM: C = scale*(A[M,K] x B[N,K]^T) (+bias). Tile 128x128, Kc=32.
// smem row: [hi 32 bf16 | lo 32 bf16] = 128B, SW128 swizzle.
// ---------------------------------------------------------------------------
#define BM 128
#define BN 128
#define NSTAGE 3
#define STAGE_BYTES 32768
#define SMEM_TOTAL (NSTAGE * STAGE_BYTES)

template <bool HAS_BIAS, bool SPLIT>
__global__ __launch_bounds__(256, 1) void gemm_bf16x3(
    const bf16* __restrict__ Ahi, const bf16* __restrict__ Alo,
    const bf16* __restrict__ Bhi, const bf16* __restrict__ Blo,
    const float* __restrict__ bias,
    float* __restrict__ C, bf16* __restrict__ Chi, bf16* __restrict__ Clo,
    int K, int lda, int ldb, int ldc,
    long aBS, long bBS, long cBS, float scale)
{
    extern __shared__ char smem[];
    const uint32_t sb = smem_u32(smem);
    const int tid = threadIdx.x;
    const int lane = tid & 31;
    const int wid = tid >> 5;
    const int wm = wid & 1;       // 0..1  (m 64-halves)
    const int wn = wid >> 1;      // 0..3  (n 32-quarters)

    const long bm = (long)blockIdx.y * BM;
    const long bn = (long)blockIdx.x * BN;
    Ahi += (long)blockIdx.z * aBS;  Alo += (long)blockIdx.z * aBS;
    Bhi += (long)blockIdx.z * bBS;  Blo += (long)blockIdx.z * bBS;
    if (SPLIT) { Chi += (long)blockIdx.z * cBS; Clo += (long)blockIdx.z * cBS; }
    else       { C   += (long)blockIdx.z * cBS; }

    const int nchunk = K >> 5;

    // ---- cp.async per-thread assignments (4 A chunks + 4 B chunks) ----
    const bf16* pA[4]; const bf16* pB[4];
    uint32_t dA[4], dB[4];
#pragma unroll
    for (int i = 0; i < 4; i++) {
        int ch = tid + i * 256;         // 0..1023
        int row = ch >> 3;
        int q = ch & 7;
        int half = q >> 2;              // 0=hi 1=lo
        int qq = q & 3;                 // 16B quarter within half
        uint32_t col = half * 64 + qq * 16;
        uint32_t sw = col ^ ((row & 7) * 16);
        dA[i] = (uint32_t)(row * 128) + sw;
        dB[i] = dA[i];
        pA[i] = (half ? Alo : Ahi) + (size_t)(bm + row) * lda + qq * 8;
        pB[i] = (half ? Blo : Bhi) + (size_t)(bn + row) * ldb + qq * 8;
    }

    // ---- ldmatrix lane address components ----
    const int rA = (lane & 7) + ((lane >> 3) & 1) * 8;
    const uint32_t cA16 = ((lane >> 4) & 1) * 16;
    const int rB = (lane & 7) + ((lane >> 4) & 1) * 8;
    const uint32_t cB16 = ((lane >> 3) & 1) * 16;

    uint32_t aoff[4], axor[4];
#pragma unroll
    for (int mt = 0; mt < 4; mt++) {
        int arow = wm * 64 + mt * 16 + rA;
        aoff[mt] = arow * 128;
        axor[mt] = (arow & 7) * 16;
    }
    uint32_t boff[2], bxor[2];
#pragma unroll
    for (int t = 0; t < 2; t++) {
        int brow = wn * 32 + t * 16 + rB;
        boff[t] = brow * 128;
        bxor[t] = (brow & 7) * 16;
    }

    float acc[4][4][4];
#pragma unroll
    for (int mt = 0; mt < 4; mt++)
#pragma unroll
        for (int nt = 0; nt < 4; nt++)
#pragma unroll
            for (int r = 0; r < 4; r++) acc[mt][nt][r] = 0.f;

    // ---- prologue: stages 0..NSTAGE-2 ----
#pragma unroll
    for (int st = 0; st < NSTAGE - 1; st++) {
        int k0 = st * 32;
        uint32_t baseA = sb + st * STAGE_BYTES;
#pragma unroll
        for (int i = 0; i < 4; i++) cp16(baseA + dA[i], pA[i] + k0);
#pragma unroll
        for (int i = 0; i < 4; i++) cp16(baseA + 16384 + dB[i], pB[i] + k0);
        cp_commit();
    }
    cp_wait<NSTAGE - 2>();
    __syncthreads();

    // ---- main loop ----
    for (int kc = 0; kc < nchunk; kc++) {
        const int stage = kc % NSTAGE;
        const uint32_t baseA = sb + stage * STAGE_BYTES;
        const uint32_t baseB = baseA + 16384;

#pragma unroll
        for (int s = 0; s < 2; s++) {
            uint32_t bh[8], bl[8];
#pragma unroll
            for (int t = 0; t < 2; t++) {
                uint32_t c = s * 32 + cB16;
                ldm4(&bh[t * 4], baseB + boff[t] + (c ^ bxor[t]));
                ldm4(&bl[t * 4], baseB + boff[t] + ((c + 64) ^ bxor[t]));
            }
#pragma unroll
            for (int mt = 0; mt < 4; mt++) {
                uint32_t a[4];
                uint32_t cc = s * 32 + cA16;
                ldm4(a, baseA + aoff[mt] + (cc ^ axor[mt]));
#pragma unroll
                for (int nt = 0; nt < 4; nt++) mma16816(acc[mt][nt], a, &bh[nt * 2]);
#pragma unroll
                for (int nt = 0; nt < 4; nt++) mma16816(acc[mt][nt], a, &bl[nt * 2]);
                ldm4(a, baseA + aoff[mt] + ((cc + 64) ^ axor[mt]));
#pragma unroll
                for (int nt = 0; nt < 4; nt++) mma16816(acc[mt][nt], a, &bh[nt * 2]);
            }
        }
        __syncthreads();

        int next = kc + NSTAGE - 1;
        if (next < nchunk) {
            int k0 = next * 32;
            uint32_t nbA = sb + (next % NSTAGE) * STAGE_BYTES;
#pragma unroll
            for (int i = 0; i < 4; i++) cp16(nbA + dA[i], pA[i] + k0);
#pragma unroll
            for (int i = 0; i < 4; i++) cp16(nbA + 16384 + dB[i], pB[i] + k0);
        }
        cp_commit();                 // empty group near the tail keeps counts exact
        cp_wait<NSTAGE - 2>();
        __syncthreads();
    }

    // ---- epilogue ----
#pragma unroll
    for (int mt = 0; mt < 4; mt++) {
        long r0 = bm + wm * 64 + mt * 16 + (lane >> 2);
        long r1 = r0 + 8;
#pragma unroll
        for (int nt = 0; nt < 4; nt++) {
            long col = bn + wn * 32 + nt * 8 + (lane & 3) * 2;
            float b0v = 0.f, b1v = 0.f;
            if (HAS_BIAS) { b0v = bias[col]; b1v = bias[col + 1]; }
            float v00 = acc[mt][nt][0] * scale + b0v;
            float v01 = acc[mt][nt][1] * scale + b1v;
            float v10 = acc[mt][nt][2] * scale + b0v;
            float v11 = acc[mt][nt][3] * scale + b1v;
            if (SPLIT) {
                bf16 h0, h1, l0, l1;
                split1(v00, h0, l0); split1(v01, h1, l1);
                *reinterpret_cast<uint32_t*>(&Chi[r0 * ldc + col]) = pack2(h0, h1);
                *reinterpret_cast<uint32_t*>(&Clo[r0 * ldc + col]) = pack2(l0, l1);
                split1(v10, h0, l0); split1(v11, h1, l1);
                *reinterpret_cast<uint32_t*>(&Chi[r1 * ldc + col]) = pack2(h0, h1);
                *reinterpret_cast<uint32_t*>(&Clo[r1 * ldc + col]) = pack2(l0, l1);
            } else {
                float2 u0 = make_float2(v00, v01);
                float2 u1 = make_float2(v10, v11);
                *reinterpret_cast<float2*>(&C[r0 * ldc + col]) = u0;
                *reinterpret_cast<float2*>(&C[r1 * ldc + col]) = u1;
            }
        }
    }
}

// ---------------------------------------------------------------------------
// fp32 -> (hi,lo) bf16 split conversion (vectorized)
// ---------------------------------------------------------------------------
__global__ __launch_bounds__(256) void split_kernel(
    const float* __restrict__ src, bf16* __restrict__ hi, bf16* __restrict__ lo, int n4)
{
    int i = blockIdx.x * blockDim.x + threadIdx.x;
    if (i >= n4) return;
    float4 v = reinterpret_cast<const float4*>(src)[i];
    bf16 h0, h1, h2, h3, l0, l1, l2, l3;
    split1(v.x, h0, l0); split1(v.y, h1, l1);
    split1(v.z, h2, l2); split1(v.w, h3, l3);
    uint2 hw = make_uint2(pack2(h0, h1), pack2(h2, h3));
    uint2 lw = make_uint2(pack2(l0, l1), pack2(l2, l3));
    reinterpret_cast<uint2*>(hi)[i] = hw;
    reinterpret_cast<uint2*>(lo)[i] = lw;
}

// ---------------------------------------------------------------------------
// V transpose (hi & lo): vt[b][e][s] = qkv[b*S+s][2E+e]
// ---------------------------------------------------------------------------
__global__ __launch_bounds__(256) void transpose_v_kernel(
    const bf16* __restrict__ qh, const bf16* __restrict__ ql,
    bf16* __restrict__ vth, bf16* __restrict__ vtl)
{
    __shared__ bf16 th[32][33];
    __shared__ bf16 tl[32][33];
    const int b = blockIdx.z;
    const int e0 = blockIdx.x * 32;
    const int s0 = blockIdx.y * 32;
    const int tx = threadIdx.x & 31;
    const int ty = threadIdx.x >> 5;  // 0..7
#pragma unroll
    for (int i = 0; i < 4; i++) {
        int s = s0 + ty + i * 8;
        size_t idx = (size_t)(b * SEQ + s) * (3 * EMBED) + 2 * EMBED + e0 + tx;
        th[ty + i * 8][tx] = qh[idx];
        tl[ty + i * 8][tx] = ql[idx];
    }
    __syncthreads();
#pragma unroll
    for (int i = 0; i < 4; i++) {
        int e = e0 + ty + i * 8;
        size_t o = (size_t)(b * EMBED + e) * SEQ + s0 + tx;
        vth[o] = th[tx][ty + i * 8];
        vtl[o] = tl[tx][ty + i * 8];
    }
}

// ---------------------------------------------------------------------------
// Row softmax with mask; writes (hi,lo) bf16 probabilities.
// ---------------------------------------------------------------------------
__global__ __launch_bounds__(256) void softmax_kernel(
    const float* __restrict__ att, const int* __restrict__ mask,
    bf16* __restrict__ phi, bf16* __restrict__ plo)
{
    const size_t row = blockIdx.x;
    const float* a = att + row * SEQ;
    const int* m = mask + row * SEQ;
    const int tid = threadIdx.x;

    __shared__ float red_max[8];
    __shared__ float red_sum[8];

    float v[8];
    float mx = -INFINITY;
#pragma unroll
    for (int i = 0; i < 8; i++) {
        int idx = tid + i * 256;
        float x = a[idx];
        x = (m[idx] != 0) ? x : -INFINITY;
        v[i] = x;
        mx = fmaxf(mx, x);
    }
#pragma unroll
    for (int o = 16; o > 0; o >>= 1)
        mx = fmaxf(mx, __shfl_xor_sync(0xffffffffu, mx, o));
    if ((tid & 31) == 0) red_max[tid >> 5] = mx;
    __syncthreads();
    float bmax = red_max[0];
#pragma unroll
    for (int w = 1; w < 8; w++) bmax = fmaxf(bmax, red_max[w]);

    float s = 0.f;
#pragma unroll
    for (int i = 0; i < 8; i++) {
        v[i] = __expf(v[i] - bmax);
        s += v[i];
    }
#pragma unroll
    for (int o = 16; o > 0; o >>= 1)
        s += __shfl_xor_sync(0xffffffffu, s, o);
    if ((tid & 31) == 0) red_sum[tid >> 5] = s;
    __syncthreads();
    float total = 0.f;
#pragma unroll
    for (int w = 0; w < 8; w++) total += red_sum[w];

    float inv = 1.f / total;
#pragma unroll
    for (int i = 0; i < 8; i++) {
        int idx = tid + i * 256;
        float p = v[i] * inv;
        bf16 h, l;
        split1(p, h, l);
        phi[row * SEQ + idx] = h;
        plo[row * SEQ + idx] = l;
    }
}

// ---------------------------------------------------------------------------
extern "C" void kernel_launch(void* const* d_in, const int* in_sizes, int n_in,
                              void* d_out, int out_size)
{
    const float* X    = (const float*)d_in[0];
    const int*   mask = (const int*)  d_in[1];
    const float* Wqkv = (const float*)d_in[2];
    const float* bqkv = (const float*)d_in[3];
    const float* Wout = (const float*)d_in[4];
    const float* bout = (const float*)d_in[5];
    float* out = (float*)d_out;

    bf16 *Xhi, *Xlo, *Wqkvhi, *Wqkvlo, *Wouthi, *Woutlo;
    bf16 *qkvhi, *qkvlo, *atthi, *attlo, *vthi, *vtlo, *ctxhi, *ctxlo;
    float* att;
    cudaGetSymbolAddress((void**)&Xhi, g_Xhi);
    cudaGetSymbolAddress((void**)&Xlo, g_Xlo);
    cudaGetSymbolAddress((void**)&Wqkvhi, g_Wqkvhi);
    cudaGetSymbolAddress((void**)&Wqkvlo, g_Wqkvlo);
    cudaGetSymbolAddress((void**)&Wouthi, g_Wouthi);
    cudaGetSymbolAddress((void**)&Woutlo, g_Woutlo);
    cudaGetSymbolAddress((void**)&qkvhi, g_qkvhi);
    cudaGetSymbolAddress((void**)&qkvlo, g_qkvlo);
    cudaGetSymbolAddress((void**)&att, g_att);
    cudaGetSymbolAddress((void**)&atthi, g_atthi);
    cudaGetSymbolAddress((void**)&attlo, g_attlo);
    cudaGetSymbolAddress((void**)&vthi, g_vthi);
    cudaGetSymbolAddress((void**)&vtlo, g_vtlo);
    cudaGetSymbolAddress((void**)&ctxhi, g_ctxhi);
    cudaGetSymbolAddress((void**)&ctxlo, g_ctxlo);

    cudaFuncSetAttribute(gemm_bf16x3<true, true>,
                         cudaFuncAttributeMaxDynamicSharedMemorySize, SMEM_TOTAL);
    cudaFuncSetAttribute(gemm_bf16x3<false, false>,
                         cudaFuncAttributeMaxDynamicSharedMemorySize, SMEM_TOTAL);
    cudaFuncSetAttribute(gemm_bf16x3<false, true>,
                         cudaFuncAttributeMaxDynamicSharedMemorySize, SMEM_TOTAL);
    cudaFuncSetAttribute(gemm_bf16x3<true, false>,
                         cudaFuncAttributeMaxDynamicSharedMemorySize, SMEM_TOTAL);

    // 0) split inputs to (hi,lo) bf16
    split_kernel<<<(ROWS * EMBED / 4 + 255) / 256, 256>>>(X, Xhi, Xlo, ROWS * EMBED / 4);
    split_kernel<<<(3 * EMBED * EMBED / 4 + 255) / 256, 256>>>(Wqkv, Wqkvhi, Wqkvlo,
                                                               3 * EMBED * EMBED / 4);
    split_kernel<<<(EMBED * EMBED / 4 + 255) / 256, 256>>>(Wout, Wouthi, Woutlo,
                                                           EMBED * EMBED / 4);

    // 1) qkv = X Wqkv^T + bqkv  (split output)
    {
        dim3 grid(3 * EMBED / BN, ROWS / BM, 1);
        gemm_bf16x3<true, true><<<grid, 256, SMEM_TOTAL>>>(
            Xhi, Xlo, Wqkvhi, Wqkvlo, bqkv,
            nullptr, qkvhi, qkvlo,
            EMBED, EMBED, EMBED, 3 * EMBED,
            0, 0, 0, 1.0f);
    }
    // 2) vt = V^T (hi,lo)
    {
        dim3 grid(EMBED / 32, SEQ / 32, BATCH);
        transpose_v_kernel<<<grid, 256>>>(qkvhi, qkvlo, vthi, vtlo);
    }
    // 3) att = Q K^T / 32  (fp32 output)
    {
        dim3 grid(SEQ / BN, SEQ / BM, BATCH);
        gemm_bf16x3<false, false><<<grid, 256, SMEM_TOTAL>>>(
            qkvhi, qkvlo, qkvhi + EMBED, qkvlo + EMBED, nullptr,
            att, nullptr, nullptr,
            EMBED, 3 * EMBED, 3 * EMBED, SEQ,
            (long)SEQ * 3 * EMBED, (long)SEQ * 3 * EMBED, (long)SEQ * SEQ,
            1.0f / 32.0f);
    }
    // 4) softmax -> (hi,lo)
    softmax_kernel<<<BATCH * SEQ, 256>>>(att, mask, atthi, attlo);

    // 5) ctx = att vt^T  (split output)
    {
        dim3 grid(EMBED / BN, SEQ / BM, BATCH);
        gemm_bf16x3<false, true><<<grid, 256, SMEM_TOTAL>>>(
            atthi, attlo, vthi, vtlo, nullptr,
            nullptr, ctxhi, ctxlo,
            SEQ, SEQ, SEQ, EMBED,
            (long)SEQ * SEQ, (long)EMBED * SEQ, (long)SEQ * EMBED,
            1.0f);
    }
    // 6) out = ctx Wout^T + bout  (fp32)
    {
        dim3 grid(EMBED / BN, ROWS / BM, 1);
        gemm_bf16x3<true, false><<<grid, 256, SMEM_TOTAL>>>(
            ctxhi, ctxlo, Wouthi, Woutlo, bout,
            out, nullptr, nullptr,
            EMBED, EMBED, EMBED, EMBED,
            0, 0, 0, 1.0f);
    }
}